// round 1
// baseline (speedup 1.0000x reference)
#include <cuda_runtime.h>
#include <cuda_bf16.h>
#include <math_constants.h>

// RationalQuadraticSpline: B=65536, V=64, K=30 bins.
// Single fused kernel: each block builds per-variable spline tables in shared
// memory (softmax widths/heights -> knots, softplus derivatives, bin LUT),
// then processes elements with float4 loads/stores, grid-stride.

#define V_VARS 64
#define KBINS  30
#define LUTN   128

__device__ __forceinline__ void rqs_one(
    float x, int v,
    const float2* __restrict__ s_wp,   // [V][30] (cumw_lo, 1/width)
    const float2* __restrict__ s_hp,   // [V][30] (cumh_lo, height)
    const float*  __restrict__ s_dv,   // [V][32] derivatives (31 used)
    const unsigned char* __restrict__ s_lut, // [V][128]
    float& o, float& l)
{
    bool outside = (x < 0.0f) || (x > 1.0f);
    float xc = fminf(fmaxf(x, 0.0f), 1.0f);
    int cell = (int)(xc * (float)LUTN);
    cell = min(cell, LUTN - 1);
    int b = (int)s_lut[v * LUTN + cell];
    // fixup scan: find largest b with cumw[b] <= x  (b in [0,29])
    #pragma unroll 1
    while (b < KBINS - 1 && xc >= s_wp[v * KBINS + b + 1].x) b++;

    float2 wp = s_wp[v * KBINS + b];
    float2 hp = s_hp[v * KBINS + b];
    float d0 = s_dv[v * 32 + b];
    float d1 = s_dv[v * 32 + b + 1];

    float icw = wp.x, invw = wp.y;
    float ich = hp.x, ih = hp.y;
    float idl = ih * invw;                 // delta = height/width

    float th   = (xc - icw) * invw;
    float omt  = 1.0f - th;
    float th2  = th * th;
    float t1mt = th * omt;

    float num  = ih * fmaf(idl, th2, d0 * t1mt);
    float den  = fmaf(d0 + d1 - 2.0f * idl, t1mt, idl);
    float rden = 1.0f / den;
    float dnum = (idl * idl) * fmaf(d1, th2, fmaf(2.0f * idl, t1mt, d0 * omt * omt));

    float oi = fmaf(num, rden, ich);
    float li = logf(dnum * rden * rden);

    o = outside ? x : oi;     // DERIV_OUT == 1 -> linear tails are identity
    l = outside ? 0.0f : li;
}

__global__ __launch_bounds__(512, 4)
void RationalQuadraticSpline_40973988004342_kernel(
    const float* __restrict__ inp,
    const float* __restrict__ uw,
    const float* __restrict__ uh,
    const float* __restrict__ ud,
    float* __restrict__ out,
    int n)
{
    __shared__ float2 s_wp[V_VARS * KBINS];
    __shared__ float2 s_hp[V_VARS * KBINS];
    __shared__ float  s_dv[V_VARS * 32];
    __shared__ unsigned char s_lut[V_VARS * LUTN];

    const int tid  = threadIdx.x;
    const int lane = tid & 31;
    const int warp = tid >> 5;              // 16 warps
    const unsigned FULL = 0xffffffffu;

    // ---- Per-variable parameter build: one warp per v, 4 v's per warp ----
    for (int v = warp; v < V_VARS; v += 16) {
        // ---------- widths ----------
        float u = (lane < KBINS) ? uw[v * KBINS + lane] : -CUDART_INF_F;
        float m = u;
        #pragma unroll
        for (int o = 16; o > 0; o >>= 1) m = fmaxf(m, __shfl_xor_sync(FULL, m, o));
        float e = (lane < KBINS) ? expf(u - m) : 0.0f;
        float s = e;
        #pragma unroll
        for (int o = 16; o > 0; o >>= 1) s += __shfl_xor_sync(FULL, s, o);
        float size = 1e-3f + (1.0f - 30.0f * 1e-3f) * (e / s);
        if (lane >= KBINS) size = 0.0f;
        // inclusive scan -> lane b holds cumw[b+1] (raw)
        float csw = size;
        #pragma unroll
        for (int o = 1; o < 32; o <<= 1) {
            float t = __shfl_up_sync(FULL, csw, o);
            if (lane >= o) csw += t;
        }
        float cplo = __shfl_up_sync(FULL, csw, 1);
        if (lane == 0) cplo = 0.0f;
        float cphi = (lane == KBINS - 1) ? 1.0f : csw;
        if (lane < KBINS) {
            float w = cphi - cplo;
            s_wp[v * KBINS + lane] = make_float2(cplo, 1.0f / w);
        }
        float cumw_knot = csw;   // lane k-1 holds cumw[k], k=1..29 valid

        // ---------- heights ----------
        float uhh = (lane < KBINS) ? uh[v * KBINS + lane] : -CUDART_INF_F;
        float mh = uhh;
        #pragma unroll
        for (int o = 16; o > 0; o >>= 1) mh = fmaxf(mh, __shfl_xor_sync(FULL, mh, o));
        float eh = (lane < KBINS) ? expf(uhh - mh) : 0.0f;
        float sh = eh;
        #pragma unroll
        for (int o = 16; o > 0; o >>= 1) sh += __shfl_xor_sync(FULL, sh, o);
        float sizeh = 1e-3f + (1.0f - 30.0f * 1e-3f) * (eh / sh);
        if (lane >= KBINS) sizeh = 0.0f;
        float csh = sizeh;
        #pragma unroll
        for (int o = 1; o < 32; o <<= 1) {
            float t = __shfl_up_sync(FULL, csh, o);
            if (lane >= o) csh += t;
        }
        float cploh = __shfl_up_sync(FULL, csh, 1);
        if (lane == 0) cploh = 0.0f;
        float cphih = (lane == KBINS - 1) ? 1.0f : csh;
        if (lane < KBINS) {
            s_hp[v * KBINS + lane] = make_float2(cploh, cphih - cploh);
        }

        // ---------- derivatives (31 knots) ----------
        if (lane < KBINS + 1) {
            const float SPC = logf(expf(1.0f - 1e-3f) - 1.0f); // pins boundary deriv to 1
            float udv = (lane == 0 || lane == KBINS) ? SPC : ud[v * (KBINS - 1) + lane - 1];
            float sp = (udv > 20.0f) ? udv : log1pf(expf(udv));
            s_dv[v * 32 + lane] = 1e-3f + sp;
        }

        // ---------- bin LUT: lut[cell] = #{k in 1..29 : cell/128 >= cumw[k]} ----------
        float c0 = (float)lane * (1.0f / (float)LUTN);
        int cnt0 = 0, cnt1 = 0, cnt2 = 0, cnt3 = 0;
        #pragma unroll 1
        for (int k = 1; k < KBINS; k++) {
            float bk = __shfl_sync(FULL, cumw_knot, k - 1);
            cnt0 += (c0 >= bk);
            cnt1 += (c0 + 32.0f / (float)LUTN >= bk);
            cnt2 += (c0 + 64.0f / (float)LUTN >= bk);
            cnt3 += (c0 + 96.0f / (float)LUTN >= bk);
        }
        s_lut[v * LUTN + lane +  0] = (unsigned char)cnt0;
        s_lut[v * LUTN + lane + 32] = (unsigned char)cnt1;
        s_lut[v * LUTN + lane + 64] = (unsigned char)cnt2;
        s_lut[v * LUTN + lane + 96] = (unsigned char)cnt3;
    }
    __syncthreads();

    // ---- Main element loop: float4 grid-stride ----
    const float4* __restrict__ in4 = (const float4*)inp;
    float4* __restrict__ out4 = (float4*)out;
    float4* __restrict__ lad4 = (float4*)(out + n);
    int n4 = n >> 2;
    int stride = gridDim.x * blockDim.x;

    for (int i = blockIdx.x * blockDim.x + tid; i < n4; i += stride) {
        float4 xv = in4[i];
        int v0 = (i << 2) & (V_VARS - 1);   // V=64, 4 | 64 -> no wrap within vector
        float4 ov, lv;
        rqs_one(xv.x, v0 + 0, s_wp, s_hp, s_dv, s_lut, ov.x, lv.x);
        rqs_one(xv.y, v0 + 1, s_wp, s_hp, s_dv, s_lut, ov.y, lv.y);
        rqs_one(xv.z, v0 + 2, s_wp, s_hp, s_dv, s_lut, ov.z, lv.z);
        rqs_one(xv.w, v0 + 3, s_wp, s_hp, s_dv, s_lut, ov.w, lv.w);
        out4[i] = ov;
        lad4[i] = lv;
    }

    // ---- Scalar tail (defensive; n is divisible by 4 for this problem) ----
    if (blockIdx.x == 0) {
        for (int e = (n & ~3) + tid; e < n; e += blockDim.x) {
            float o, l;
            rqs_one(inp[e], e & (V_VARS - 1), s_wp, s_hp, s_dv, s_lut, o, l);
            out[e] = o;
            out[n + e] = l;
        }
    }
}

extern "C" void kernel_launch(void* const* d_in, const int* in_sizes, int n_in,
                              void* d_out, int out_size)
{
    const float* inp = (const float*)d_in[0];
    const float* uw  = (const float*)d_in[1];
    const float* uh  = (const float*)d_in[2];
    const float* ud  = (const float*)d_in[3];
    float* out = (float*)d_out;
    int n = in_sizes[0];

    int n4 = n >> 2;
    int blocks = 608;                       // 152 SMs x 4 resident blocks
    int maxb = (n4 + 511) / 512;
    if (maxb < 1) maxb = 1;
    if (blocks > maxb) blocks = maxb;

    RationalQuadraticSpline_40973988004342_kernel<<<blocks, 512>>>(inp, uw, uh, ud, out, n);
}

// round 2
// speedup vs baseline: 1.4938x; 1.4938x over previous
#include <cuda_runtime.h>
#include <cuda_bf16.h>
#include <math_constants.h>

// RationalQuadraticSpline: B=65536, V=64, K=30 bins.
// Two-kernel plan:
//   K1 (1 block): build per-variable spline tables + 512-cell bin LUT into
//                 __device__ globals.
//   K2 (304 blocks x 512): copy tables to smem, process elements float4-wide
//                 with branchless 2-step bin fixup and fast log/rcp.

#define V_VARS 64
#define KBINS  30
#define LUTN   512

// Packed tables: per (v, bin) two float4s, bins padded to 32 with sentinels.
//   Q0 = (icw, invw, ich, ih)
//   Q1 = (idl, d0, c=d0+d1-2*idl, idl2=idl*idl)
__device__ float4        g_tab[V_VARS * 32 * 2];
__device__ unsigned char g_lut[V_VARS * LUTN];

// ---------------------------------------------------------------------------
// Build kernel: 1 block, 1024 threads (32 warps). Warp w builds v = w, w+32.
// ---------------------------------------------------------------------------
__global__ __launch_bounds__(1024, 1)
void rqs_build_kernel(const float* __restrict__ uw,
                      const float* __restrict__ uh,
                      const float* __restrict__ ud)
{
    __shared__ float         s_cw[V_VARS * 31];       // knots cw[0..30] per v
    __shared__ unsigned char s_lutb[V_VARS * LUTN];

    const int tid  = threadIdx.x;
    const int lane = tid & 31;
    const int warp = tid >> 5;
    const unsigned FULL = 0xffffffffu;

    for (int v = warp; v < V_VARS; v += 32) {
        // ---------- widths: softmax + floor + scan ----------
        float u = (lane < KBINS) ? uw[v * KBINS + lane] : -CUDART_INF_F;
        float m = u;
        #pragma unroll
        for (int o = 16; o > 0; o >>= 1) m = fmaxf(m, __shfl_xor_sync(FULL, m, o));
        float e = (lane < KBINS) ? expf(u - m) : 0.0f;
        float s = e;
        #pragma unroll
        for (int o = 16; o > 0; o >>= 1) s += __shfl_xor_sync(FULL, s, o);
        float size = 1e-3f + (1.0f - 30.0f * 1e-3f) * (e / s);
        if (lane >= KBINS) size = 0.0f;
        float csw = size;
        #pragma unroll
        for (int o = 1; o < 32; o <<= 1) {
            float t = __shfl_up_sync(FULL, csw, o);
            if (lane >= o) csw += t;
        }
        float cplo = __shfl_up_sync(FULL, csw, 1);
        if (lane == 0) cplo = 0.0f;
        float cphi = (lane == KBINS - 1) ? 1.0f : csw;
        float w    = cphi - cplo;
        float invw = 1.0f / w;

        // ---------- heights ----------
        float uhh = (lane < KBINS) ? uh[v * KBINS + lane] : -CUDART_INF_F;
        float mh = uhh;
        #pragma unroll
        for (int o = 16; o > 0; o >>= 1) mh = fmaxf(mh, __shfl_xor_sync(FULL, mh, o));
        float eh = (lane < KBINS) ? expf(uhh - mh) : 0.0f;
        float sh = eh;
        #pragma unroll
        for (int o = 16; o > 0; o >>= 1) sh += __shfl_xor_sync(FULL, sh, o);
        float sizeh = 1e-3f + (1.0f - 30.0f * 1e-3f) * (eh / sh);
        if (lane >= KBINS) sizeh = 0.0f;
        float csh = sizeh;
        #pragma unroll
        for (int o = 1; o < 32; o <<= 1) {
            float t = __shfl_up_sync(FULL, csh, o);
            if (lane >= o) csh += t;
        }
        float cploh = __shfl_up_sync(FULL, csh, 1);
        if (lane == 0) cploh = 0.0f;
        float cphih = (lane == KBINS - 1) ? 1.0f : csh;
        float hgt   = cphih - cploh;

        // ---------- derivatives: lanes 0..30 hold d[lane] ----------
        const float SPC = logf(expf(1.0f - 1e-3f) - 1.0f); // pins boundary to 1
        float udv = (lane == 0 || lane >= KBINS) ? SPC : ud[v * (KBINS - 1) + lane - 1];
        float sp  = (udv > 20.0f) ? udv : log1pf(expf(udv));
        float d0  = 1e-3f + sp;
        float d1  = __shfl_down_sync(FULL, d0, 1);

        // ---------- pack and store tables ----------
        float idl  = hgt * invw;
        float c    = d0 + d1 - 2.0f * idl;
        float idl2 = idl * idl;
        int base = (v * 32 + lane) * 2;
        if (lane < KBINS) {
            g_tab[base]     = make_float4(cplo, invw, cploh, hgt);
            g_tab[base + 1] = make_float4(idl, d0, c, idl2);
        } else {
            g_tab[base]     = make_float4(1e9f, 1.0f, 1.0f, 1.0f); // sentinel icw
            g_tab[base + 1] = make_float4(1.0f, 1.0f, 1.0f, 1.0f);
        }

        // knots for LUT fill
        if (lane < KBINS) s_cw[v * 31 + lane] = cplo;
        if (lane == 0)    s_cw[v * 31 + KBINS] = 1.0f;
    }
    __syncthreads();

    // ---------- LUT fill: cell c -> largest bin k with cw[k] <= c/512 ----------
    for (int j = tid; j < V_VARS * KBINS; j += blockDim.x) {
        int v = j / KBINS;
        int k = j - v * KBINS;
        float lo_f = s_cw[v * 31 + k];
        float hi_f = s_cw[v * 31 + k + 1];
        int lo = (int)ceilf(lo_f * (float)LUTN);
        int hi = (int)ceilf(hi_f * (float)LUTN);
        if (lo < 0) lo = 0;
        if (hi > LUTN) hi = LUTN;
        for (int cix = lo; cix < hi; cix++)
            s_lutb[v * LUTN + cix] = (unsigned char)k;
    }
    __syncthreads();

    // copy LUT to global (int4 granularity)
    const int4* src = (const int4*)s_lutb;
    int4* dst = (int4*)g_lut;
    for (int i = tid; i < (V_VARS * LUTN) / 16; i += blockDim.x)
        dst[i] = src[i];
}

// ---------------------------------------------------------------------------
// Main kernel
// ---------------------------------------------------------------------------
__device__ __forceinline__ void rqs_eval(
    float x,
    const float4* __restrict__ tab,           // this variable's 32-bin table
    const unsigned char* __restrict__ lut,    // this variable's 512-cell LUT
    float& o, float& l)
{
    float xc = __saturatef(x);
    int cell = min((int)(xc * (float)LUTN), LUTN - 1);
    int b = (int)lut[cell];
    // branchless exact fixup: <=2 knots per LUT cell (cell 1.95e-3 < 2*min_bw)
    const float* cw = (const float*)tab;      // icw at float index bin*8
    b += (xc >= cw[(b + 1) << 3]);
    b += (xc >= cw[(b + 1) << 3]);

    float4 q0 = tab[b * 2];       // icw, invw, ich, ih
    float4 q1 = tab[b * 2 + 1];   // idl, d0, c, idl2

    float th   = (xc - q0.x) * q0.y;
    float th2  = th * th;
    float t1mt = th - th2;
    float h    = q1.x - q1.y;                       // idl - d0
    float np   = fmaf(h, th, q1.y);                 // d0 + (idl-d0)*th
    float den  = fmaf(q1.z, t1mt, q1.x);
    float rden = __fdividef(1.0f, den);
    float tnum = (q0.w * th) * np;                  // ih*th*np
    float oi   = fmaf(tnum, rden, q0.z);
    float poly = fmaf(fmaf(q1.z, th, h + h), th, q1.y);
    float dnum = q1.w * poly;
    float li   = __logf(dnum * rden * rden);

    bool inside = (x == xc);
    o = inside ? oi : x;          // DERIV_OUT == 1 -> linear tails are identity
    l = inside ? li : 0.0f;
}

__global__ __launch_bounds__(512)
void RationalQuadraticSpline_40973988004342_kernel(
    const float* __restrict__ inp,
    float* __restrict__ out,
    int n)
{
    extern __shared__ float4 smem[];
    float4* s_tab = smem;                                   // 4096 float4 = 64KB
    unsigned char* s_lut = (unsigned char*)(smem + V_VARS * 32 * 2);  // 32KB

    const int tid = threadIdx.x;

    // copy tables from global into smem
    for (int i = tid; i < V_VARS * 32 * 2; i += blockDim.x)
        s_tab[i] = g_tab[i];
    {
        const int4* src = (const int4*)g_lut;
        int4* dst = (int4*)s_lut;
        for (int i = tid; i < (V_VARS * LUTN) / 16; i += blockDim.x)
            dst[i] = src[i];
    }
    __syncthreads();

    int g = blockIdx.x * blockDim.x + tid;
    // v of element 4*g is constant across grid-stride iters (stride % 16 == 0)
    int vA = (g << 2) & (V_VARS - 1);
    const float4* tA = s_tab + (vA + 0) * 64;
    const float4* tB = s_tab + (vA + 1) * 64;
    const float4* tC = s_tab + (vA + 2) * 64;
    const float4* tD = s_tab + (vA + 3) * 64;
    const unsigned char* lA = s_lut + (vA + 0) * LUTN;
    const unsigned char* lB = s_lut + (vA + 1) * LUTN;
    const unsigned char* lC = s_lut + (vA + 2) * LUTN;
    const unsigned char* lD = s_lut + (vA + 3) * LUTN;

    const float4* __restrict__ in4 = (const float4*)inp;
    float4* __restrict__ out4 = (float4*)out;
    float4* __restrict__ lad4 = (float4*)(out + n);
    int n4 = n >> 2;
    int stride = gridDim.x * blockDim.x;

    for (int i = g; i < n4; i += stride) {
        float4 xv = in4[i];
        float4 ov, lv;
        rqs_eval(xv.x, tA, lA, ov.x, lv.x);
        rqs_eval(xv.y, tB, lB, ov.y, lv.y);
        rqs_eval(xv.z, tC, lC, ov.z, lv.z);
        rqs_eval(xv.w, tD, lD, ov.w, lv.w);
        out4[i] = ov;
        lad4[i] = lv;
    }

    // defensive scalar tail (n divisible by 4 for this problem)
    if (blockIdx.x == 0) {
        for (int e = (n & ~3) + tid; e < n; e += blockDim.x) {
            int v = e & (V_VARS - 1);
            float o, l;
            rqs_eval(inp[e], s_tab + v * 64, s_lut + v * LUTN, o, l);
            out[e] = o;
            out[n + e] = l;
        }
    }
}

extern "C" void kernel_launch(void* const* d_in, const int* in_sizes, int n_in,
                              void* d_out, int out_size)
{
    const float* inp = (const float*)d_in[0];
    const float* uw  = (const float*)d_in[1];
    const float* uh  = (const float*)d_in[2];
    const float* ud  = (const float*)d_in[3];
    float* out = (float*)d_out;
    int n = in_sizes[0];

    const int MAIN_SMEM = (V_VARS * 32 * 2) * 16 + V_VARS * LUTN;  // 98304 B
    cudaFuncSetAttribute(RationalQuadraticSpline_40973988004342_kernel,
                         cudaFuncAttributeMaxDynamicSharedMemorySize, MAIN_SMEM);

    rqs_build_kernel<<<1, 1024>>>(uw, uh, ud);

    int n4 = n >> 2;
    int blocks = 304;                        // 152 SMs x 2 resident blocks
    int maxb = (n4 + 511) / 512;
    if (maxb < 1) maxb = 1;
    if (blocks > maxb) blocks = maxb;

    RationalQuadraticSpline_40973988004342_kernel<<<blocks, 512, MAIN_SMEM>>>(inp, out, n);
}

// round 3
// speedup vs baseline: 2.4725x; 1.6552x over previous
#include <cuda_runtime.h>
#include <cuda_bf16.h>
#include <math_constants.h>

// RationalQuadraticSpline: B=65536, V=64, K=30 bins.
//   K1 (64 blocks, one per variable): build packed tables + 512-cell LUT.
//   K2 (304 blocks x 512): smem tables, float4 grid-stride eval.
// Smem layout engineered for bank-conflict-light gathers:
//   A[v][32] float4 (icw,invw,ich,ih)   -> 16B-group = b mod 8 (full spread)
//   D[v][32] float2 (d0,d1)             -> LDS.64
//   KN[v][33] float knots (stride 33)   -> bank = (v+b) mod 32
//   LUT[v][512] u8                      -> random banks

#define V_VARS 64
#define KBINS  30
#define LUTN   512

__device__ float4        g_A[V_VARS * 32];
__device__ float2        g_D[V_VARS * 32];
__device__ float         g_kn[V_VARS * 33];
__device__ unsigned char g_lut[V_VARS * LUTN];

// ---------------------------------------------------------------------------
// Build kernel: one block per variable, 128 threads. Warp 0 computes params.
// ---------------------------------------------------------------------------
__global__ __launch_bounds__(128, 8)
void rqs_build_kernel(const float* __restrict__ uw,
                      const float* __restrict__ uh,
                      const float* __restrict__ ud)
{
    __shared__ float s_kn[33];

    const int v    = blockIdx.x;
    const int tid  = threadIdx.x;
    const int lane = tid & 31;
    const unsigned FULL = 0xffffffffu;

    if (tid < 32) {
        // ---------- widths: softmax + floor + scan ----------
        float u = (lane < KBINS) ? uw[v * KBINS + lane] : -CUDART_INF_F;
        float m = u;
        #pragma unroll
        for (int o = 16; o > 0; o >>= 1) m = fmaxf(m, __shfl_xor_sync(FULL, m, o));
        float e = (lane < KBINS) ? expf(u - m) : 0.0f;
        float s = e;
        #pragma unroll
        for (int o = 16; o > 0; o >>= 1) s += __shfl_xor_sync(FULL, s, o);
        float size = 1e-3f + (1.0f - 30.0f * 1e-3f) * (e / s);
        if (lane >= KBINS) size = 0.0f;
        float csw = size;
        #pragma unroll
        for (int o = 1; o < 32; o <<= 1) {
            float t = __shfl_up_sync(FULL, csw, o);
            if (lane >= o) csw += t;
        }
        float cplo = __shfl_up_sync(FULL, csw, 1);
        if (lane == 0) cplo = 0.0f;
        float cphi = (lane == KBINS - 1) ? 1.0f : csw;
        float invw = 1.0f / (cphi - cplo);

        // ---------- heights ----------
        float uhh = (lane < KBINS) ? uh[v * KBINS + lane] : -CUDART_INF_F;
        float mh = uhh;
        #pragma unroll
        for (int o = 16; o > 0; o >>= 1) mh = fmaxf(mh, __shfl_xor_sync(FULL, mh, o));
        float eh = (lane < KBINS) ? expf(uhh - mh) : 0.0f;
        float sh = eh;
        #pragma unroll
        for (int o = 16; o > 0; o >>= 1) sh += __shfl_xor_sync(FULL, sh, o);
        float sizeh = 1e-3f + (1.0f - 30.0f * 1e-3f) * (eh / sh);
        if (lane >= KBINS) sizeh = 0.0f;
        float csh = sizeh;
        #pragma unroll
        for (int o = 1; o < 32; o <<= 1) {
            float t = __shfl_up_sync(FULL, csh, o);
            if (lane >= o) csh += t;
        }
        float cploh = __shfl_up_sync(FULL, csh, 1);
        if (lane == 0) cploh = 0.0f;
        float cphih = (lane == KBINS - 1) ? 1.0f : csh;
        float hgt = cphih - cploh;

        // ---------- derivatives: lane k holds d[k], k=0..30 ----------
        const float SPC = logf(expf(1.0f - 1e-3f) - 1.0f);  // pins boundary to 1
        float udv = (lane == 0 || lane >= KBINS) ? SPC : ud[v * (KBINS - 1) + lane - 1];
        float sp  = (udv > 20.0f) ? udv : log1pf(expf(udv));
        float d0  = 1e-3f + sp;
        float d1  = __shfl_down_sync(FULL, d0, 1);

        // ---------- store ----------
        if (lane < KBINS) {
            g_A[v * 32 + lane] = make_float4(cplo, invw, cploh, hgt);
            g_D[v * 32 + lane] = make_float2(d0, d1);
        } else {
            g_A[v * 32 + lane] = make_float4(0.f, 1.f, 0.f, 0.f);
            g_D[v * 32 + lane] = make_float2(1.f, 1.f);
        }
        // knots for fixup compares: kn[k] = cumw[k], k=0..29; kn[30]=1+EPS; kn[31]=2
        float kn;
        if (lane < KBINS)            kn = cplo;
        else if (lane == KBINS)      kn = 1.0f + 1e-6f;
        else                         kn = 2.0f;
        g_kn[v * 33 + lane] = kn;
        if (lane == 32 - 1) g_kn[v * 33 + 32] = 2.0f;  // pad
        s_kn[lane] = kn;
    }
    __syncthreads();

    // ---------- LUT: cell c -> #{k in 1..29 : kn[k] <= c/512} ----------
    for (int c = tid; c < LUTN; c += blockDim.x) {
        float cf = (float)c * (1.0f / (float)LUTN);   // exact (pow2 scale)
        int cnt = 0;
        #pragma unroll
        for (int k = 1; k < KBINS; k++) cnt += (cf >= s_kn[k]);
        g_lut[v * LUTN + c] = (unsigned char)cnt;
    }
}

// ---------------------------------------------------------------------------
// Main kernel
// ---------------------------------------------------------------------------
__device__ __forceinline__ void rqs_eval(
    float x,
    const float4* __restrict__ Av,
    const float2* __restrict__ Dv,
    const float*  __restrict__ KNv,
    const unsigned char* __restrict__ Lv,
    float& o, float& l)
{
    float xc = __saturatef(x);
    int cell = min((int)(xc * (float)LUTN), LUTN - 1);
    int b = (int)Lv[cell];
    // exact branchless fixup: <=2 knots per 1.95e-3 cell (min bin width 1e-3)
    b += (xc >= KNv[b + 1]);
    b += (xc >= KNv[b + 1]);

    float4 q0 = Av[b];          // icw, invw, ich, ih
    float2 dd = Dv[b];          // d0, d1

    float d0  = dd.x;
    float idl = q0.w * q0.y;                       // height/width
    float cc  = (d0 + dd.y) - 2.0f * idl;
    float h   = idl - d0;

    float th   = (xc - q0.x) * q0.y;
    float th2  = th * th;
    float t1mt = th - th2;

    float np   = fmaf(h, th, d0);                  // d0 + (idl-d0)*th
    float den  = fmaf(cc, t1mt, idl);
    float rden = __fdividef(1.0f, den);
    float oi   = fmaf((q0.w * th) * np, rden, q0.z);
    float poly = fmaf(fmaf(cc, th, h + h), th, d0);
    float li   = __logf((idl * idl) * poly * (rden * rden));

    bool inside = (x == xc);
    o = inside ? oi : x;        // DERIV_OUT == 1 -> linear tails are identity
    l = inside ? li : 0.0f;
}

__global__ __launch_bounds__(512)
void RationalQuadraticSpline_40973988004342_kernel(
    const float* __restrict__ inp,
    float* __restrict__ out,
    int n)
{
    extern __shared__ unsigned char smem[];
    float4*        s_A  = (float4*)smem;                            // 32 KB
    float2*        s_D  = (float2*)(smem + 32768);                  // 16 KB
    unsigned char* s_L  = smem + 32768 + 16384;                     // 32 KB
    float*         s_KN = (float*)(smem + 32768 + 16384 + 32768);   // 8448 B

    const int tid = threadIdx.x;

    // table copy from global
    {
        const int4* sa = (const int4*)g_A;
        int4* da = (int4*)s_A;
        for (int i = tid; i < V_VARS * 32; i += blockDim.x) da[i] = sa[i];
        const int4* sd = (const int4*)g_D;
        int4* dd4 = (int4*)s_D;
        for (int i = tid; i < V_VARS * 16; i += blockDim.x) dd4[i] = sd[i];
        const int4* sl = (const int4*)g_lut;
        int4* dl = (int4*)s_L;
        for (int i = tid; i < (V_VARS * LUTN) / 16; i += blockDim.x) dl[i] = sl[i];
        for (int i = tid; i < V_VARS * 33; i += blockDim.x) s_KN[i] = g_kn[i];
    }
    __syncthreads();

    int g = blockIdx.x * blockDim.x + tid;
    // v of element 4*g is constant across grid-stride iters (stride % 16 == 0)
    int vA = (g << 2) & (V_VARS - 1);
    const float4* tA0 = s_A + (vA + 0) * 32;
    const float4* tA1 = s_A + (vA + 1) * 32;
    const float4* tA2 = s_A + (vA + 2) * 32;
    const float4* tA3 = s_A + (vA + 3) * 32;
    const float2* tD0 = s_D + (vA + 0) * 32;
    const float2* tD1 = s_D + (vA + 1) * 32;
    const float2* tD2 = s_D + (vA + 2) * 32;
    const float2* tD3 = s_D + (vA + 3) * 32;
    const float* k0 = s_KN + (vA + 0) * 33;
    const float* k1 = s_KN + (vA + 1) * 33;
    const float* k2 = s_KN + (vA + 2) * 33;
    const float* k3 = s_KN + (vA + 3) * 33;
    const unsigned char* l0 = s_L + (vA + 0) * LUTN;
    const unsigned char* l1 = s_L + (vA + 1) * LUTN;
    const unsigned char* l2 = s_L + (vA + 2) * LUTN;
    const unsigned char* l3 = s_L + (vA + 3) * LUTN;

    const float4* __restrict__ in4 = (const float4*)inp;
    float4* __restrict__ out4 = (float4*)out;
    float4* __restrict__ lad4 = (float4*)(out + n);
    int n4 = n >> 2;
    int stride = gridDim.x * blockDim.x;

    for (int i = g; i < n4; i += stride) {
        float4 xv = in4[i];
        float4 ov, lv;
        rqs_eval(xv.x, tA0, tD0, k0, l0, ov.x, lv.x);
        rqs_eval(xv.y, tA1, tD1, k1, l1, ov.y, lv.y);
        rqs_eval(xv.z, tA2, tD2, k2, l2, ov.z, lv.z);
        rqs_eval(xv.w, tA3, tD3, k3, l3, ov.w, lv.w);
        out4[i] = ov;
        lad4[i] = lv;
    }

    // defensive scalar tail (n divisible by 4 for this problem)
    if (blockIdx.x == 0) {
        for (int e = (n & ~3) + tid; e < n; e += blockDim.x) {
            int v = e & (V_VARS - 1);
            float o, l;
            rqs_eval(inp[e], s_A + v * 32, s_D + v * 32, s_KN + v * 33,
                     s_L + v * LUTN, o, l);
            out[e] = o;
            out[n + e] = l;
        }
    }
}

extern "C" void kernel_launch(void* const* d_in, const int* in_sizes, int n_in,
                              void* d_out, int out_size)
{
    const float* inp = (const float*)d_in[0];
    const float* uw  = (const float*)d_in[1];
    const float* uh  = (const float*)d_in[2];
    const float* ud  = (const float*)d_in[3];
    float* out = (float*)d_out;
    int n = in_sizes[0];

    const int MAIN_SMEM = 32768 + 16384 + 32768 + V_VARS * 33 * 4;  // 90368 B
    static int configured = -1;
    if (configured != MAIN_SMEM) {
        cudaFuncSetAttribute(RationalQuadraticSpline_40973988004342_kernel,
                             cudaFuncAttributeMaxDynamicSharedMemorySize, MAIN_SMEM);
        configured = MAIN_SMEM;
    }

    rqs_build_kernel<<<V_VARS, 128>>>(uw, uh, ud);

    int n4 = n >> 2;
    int blocks = 304;                        // 152 SMs x 2 resident blocks
    int maxb = (n4 + 511) / 512;
    if (maxb < 1) maxb = 1;
    if (blocks > maxb) blocks = maxb;

    RationalQuadraticSpline_40973988004342_kernel<<<blocks, 512, MAIN_SMEM>>>(inp, out, n);
}